// round 10
// baseline (speedup 1.0000x reference)
#include <cuda_runtime.h>
#include <math.h>
#include <float.h>

#define G 20
#define GC (G * G * G)   // 8000
#define NB 4             // batches
#define NCB 8            // cloud*NB + b
#define NPC 8192         // max points per (cloud,batch)
#define GMIN (-5.0f)
#define GH 0.5f
#define GINV 2.0f

// Static scratch (no cudaMalloc anywhere).
__device__ int g_cnt[NCB][GC];
__device__ int g_start[NCB][GC + 1];
__device__ int g_cid[NCB][NPC];
__device__ int g_rnk[NCB][NPC];
__device__ float4 g_pts[NCB][NPC];  // cell-sorted (x, y, z, |p|^2/2)
__device__ float g_part[1024];
__device__ unsigned g_barcnt = 0;
__device__ unsigned g_bargen = 0;

// Self-resetting grid barrier (256 blocks: always co-resident).
__device__ __forceinline__ void gridbar() {
    __syncthreads();
    if (threadIdx.x == 0) {
        __threadfence();
        unsigned gen = atomicAdd(&g_bargen, 0u);
        if (atomicAdd(&g_barcnt, 1u) == gridDim.x - 1) {
            atomicExch(&g_barcnt, 0u);
            __threadfence();
            atomicAdd(&g_bargen, 1u);
        } else {
            while (atomicAdd(&g_bargen, 0u) == gen) __nanosleep(64);
        }
        __threadfence();
    }
    __syncthreads();
}

__device__ __forceinline__ int cellof(float x) {
    int c = (int)((x - GMIN) * GINV);
    return min(G - 1, max(0, c));
}

// ---------- prep: zero -> count -> scan -> scatter (persistent, 3 barriers) ----------
__global__ __launch_bounds__(256) void prep_kernel(const float* __restrict__ in1,
                                                   const float* __restrict__ in2,
                                                   int N, int M) {
    const int tid = threadIdx.x;
    const int gid = blockIdx.x * 256 + tid;
    const int gsz = gridDim.x * 256;
    const int tot1 = NB * N;
    const int total = tot1 + NB * M;

    // Zero counters.
    for (int j = gid; j < NCB * GC; j += gsz) ((int*)g_cnt)[j] = 0;
    gridbar();

    // Count: cell id + rank per point.
    for (int i = gid; i < total; i += gsz) {
        const float* p;
        int cb, slot;
        if (i < tot1) { cb = i / N; slot = i - cb * N; p = in1 + (size_t)i * 3; }
        else {
            int j = i - tot1;
            cb = NB + j / M;
            slot = j - (cb - NB) * M;
            p = in2 + (size_t)j * 3;
        }
        int cid = (cellof(p[2]) * G + cellof(p[1])) * G + cellof(p[0]);
        g_cid[cb][slot] = cid;
        g_rnk[cb][slot] = atomicAdd(&g_cnt[cb][cid], 1);
    }
    gridbar();

    // Scan: one block per (cloud,batch); 256 threads x 32 cells = 8192 >= GC.
    if (blockIdx.x < NCB) {
        const int cb = blockIdx.x;
        const int base = tid * 32;
        int loc = 0;
#pragma unroll 4
        for (int i = 0; i < 32; i++) {
            int c = base + i;
            if (c < GC) loc += g_cnt[cb][c];
        }
        __shared__ int sh[256];
        sh[tid] = loc;
        __syncthreads();
        for (int off = 1; off < 256; off <<= 1) {
            int v = (tid >= off) ? sh[tid - off] : 0;
            __syncthreads();
            sh[tid] += v;
            __syncthreads();
        }
        int excl = sh[tid] - loc;
#pragma unroll 4
        for (int i = 0; i < 32; i++) {
            int c = base + i;
            if (c < GC) {
                int v = g_cnt[cb][c];
                g_start[cb][c] = excl;
                excl += v;
            }
        }
        if (tid == 255) g_start[cb][GC] = sh[255];
    }
    gridbar();

    // Scatter into cell-sorted order; carry |p|^2/2.
    for (int i = gid; i < total; i += gsz) {
        const float* p;
        int cb, slot;
        if (i < tot1) { cb = i / N; slot = i - cb * N; p = in1 + (size_t)i * 3; }
        else {
            int j = i - tot1;
            cb = NB + j / M;
            slot = j - (cb - NB) * M;
            p = in2 + (size_t)j * 3;
        }
        const float x = p[0], y = p[1], z = p[2];
        const int pos = g_start[cb][g_cid[cb][slot]] + g_rnk[cb][slot];
        g_pts[cb][pos] = make_float4(x, y, z, 0.5f * (x * x + y * y + z * z));
    }
}

// ---------- search: 4 threads per query; incremental ring shells ----------
// t = h_p - q.p per candidate; d^2 = 2*(tmin + g_q). Unscanned cells are
// Chebyshev >= R+1 away -> separation >= R*GH (boundary-clamp safe).
__global__ __launch_bounds__(256) void search_kernel(int N, int M,
                                                     float inv0, float inv1) {
    const int tid = threadIdx.x;
    const int gid = blockIdx.x * 256 + tid;
    const int qi = gid >> 2;
    const int sub = gid & 3;
    const unsigned qmask = 0xFu << (tid & 28);  // quad lanes (convergent)
    const int tot1 = NB * N;
    const int total = tot1 + NB * M;

    float contrib = 0.f;
    if (qi < total) {
        int qcb, rcb;
        float wgt;
        if (qi < tot1) { qcb = qi / N; rcb = NB + qcb; wgt = inv1; }
        else { int j = qi - tot1; qcb = NB + j / M; rcb = qcb - NB; wgt = inv0; }
        const int slot = (qi < tot1) ? (qi % N) : ((qi - tot1) % M);

        const float4 q = g_pts[qcb][slot];  // quad-uniform broadcast
        const float nqx = -q.x, nqy = -q.y, nqz = -q.z, gq = q.w;
        const int cx = cellof(q.x), cy = cellof(q.y), cz = cellof(q.z);

        const float4* __restrict__ pts = g_pts[rcb];
        const int* __restrict__ cs = g_start[rcb];

        float tmin = FLT_MAX;
        float best;

        // R = 1: full 3^3 box; rows (z,y) round-robin over the 4 sub-threads.
        {
            const int z0 = max(cz - 1, 0), z1 = min(cz + 1, G - 1);
            const int y0 = max(cy - 1, 0), y1 = min(cy + 1, G - 1);
            const int x0 = max(cx - 1, 0), x1 = min(cx + 1, G - 1);
            int ridx = 0;
            for (int z = z0; z <= z1; z++) {
                for (int y = y0; y <= y1; y++) {
                    if ((ridx++ & 3) == sub) {
                        const int rowb = (z * G + y) * G;
                        const int s = cs[rowb + x0];
                        const int e = cs[rowb + x1 + 1];
                        for (int k = s; k < e; k++) {
                            float4 p = pts[k];
                            float t = fmaf(p.x, nqx, fmaf(p.y, nqy, fmaf(p.z, nqz, p.w)));
                            tmin = fminf(tmin, t);
                        }
                    }
                }
            }
        }
        tmin = fminf(tmin, __shfl_xor_sync(qmask, tmin, 1));
        tmin = fminf(tmin, __shfl_xor_sync(qmask, tmin, 2));
        best = fmaxf(0.f, 2.f * (tmin + gq));

        // Expand shells only if needed (~0.6% of queries at h=0.5).
        for (int R = 2; best > (float)(R - 1) * GH * (float)(R - 1) * GH && R <= G; R++) {
            const int z0 = max(cz - R, 0), z1 = min(cz + R, G - 1);
            const int y0 = max(cy - R, 0), y1 = min(cy + R, G - 1);
            const int x0 = max(cx - R, 0), x1 = min(cx + R, G - 1);
            const int xl = cx - R, xh = cx + R;
            int ridx = 0;
            for (int z = z0; z <= z1; z++) {
                const int adz = (z > cz) ? (z - cz) : (cz - z);
                for (int y = y0; y <= y1; y++) {
                    const int ady = (y > cy) ? (y - cy) : (cy - y);
                    if ((ridx++ & 3) != sub) continue;
                    const int rowb = (z * G + y) * G;
                    if (adz == R || ady == R) {
                        // boundary row: full new x-range
                        const int s = cs[rowb + x0];
                        const int e = cs[rowb + x1 + 1];
                        for (int k = s; k < e; k++) {
                            float4 p = pts[k];
                            float t = fmaf(p.x, nqx, fmaf(p.y, nqy, fmaf(p.z, nqz, p.w)));
                            tmin = fminf(tmin, t);
                        }
                    } else {
                        // interior row: only the two new end cells
                        if (xl >= 0) {
                            const int s = cs[rowb + xl], e = cs[rowb + xl + 1];
                            for (int k = s; k < e; k++) {
                                float4 p = pts[k];
                                float t = fmaf(p.x, nqx, fmaf(p.y, nqy, fmaf(p.z, nqz, p.w)));
                                tmin = fminf(tmin, t);
                            }
                        }
                        if (xh <= G - 1) {
                            const int s = cs[rowb + xh], e = cs[rowb + xh + 1];
                            for (int k = s; k < e; k++) {
                                float4 p = pts[k];
                                float t = fmaf(p.x, nqx, fmaf(p.y, nqy, fmaf(p.z, nqz, p.w)));
                                tmin = fminf(tmin, t);
                            }
                        }
                    }
                }
            }
            tmin = fminf(tmin, __shfl_xor_sync(qmask, tmin, 1));
            tmin = fminf(tmin, __shfl_xor_sync(qmask, tmin, 2));
            best = fmaxf(0.f, 2.f * (tmin + gq));
        }

        if (sub == 0) contrib = sqrtf(best) * wgt;
    }

    // Deterministic per-block reduction (fixed thread->query mapping).
    float acc = contrib;
#pragma unroll
    for (int off = 16; off > 0; off >>= 1)
        acc += __shfl_down_sync(0xFFFFFFFFu, acc, off);
    __shared__ float shf[8];
    if ((tid & 31) == 0) shf[tid >> 5] = acc;
    __syncthreads();
    if (tid < 8) {
        float v = shf[tid];
#pragma unroll
        for (int off = 4; off > 0; off >>= 1)
            v += __shfl_down_sync(0xFFu, v, off);
        if (tid == 0) g_part[blockIdx.x] = v;
    }
}

// ---------- final: fixed-order sum of block partials ----------
__global__ void final_kernel(float* __restrict__ out, int nPart) {
    float a = 0.f;
    for (int k = threadIdx.x; k < nPart; k += 256) a += g_part[k];
#pragma unroll
    for (int off = 16; off > 0; off >>= 1)
        a += __shfl_down_sync(0xFFFFFFFFu, a, off);
    __shared__ float s[8];
    if ((threadIdx.x & 31) == 0) s[threadIdx.x >> 5] = a;
    __syncthreads();
    if (threadIdx.x < 8) {
        float v = s[threadIdx.x];
#pragma unroll
        for (int off = 4; off > 0; off >>= 1)
            v += __shfl_down_sync(0xFFu, v, off);
        if (threadIdx.x == 0) out[0] = v;
    }
}

extern "C" void kernel_launch(void* const* d_in, const int* in_sizes, int n_in,
                              void* d_out, int out_size) {
    const float* in1 = (const float*)d_in[0];  // [B, N, 3] cloud1
    const float* in2 = (const float*)d_in[1];  // [B, M, 3] cloud2
    const int N = in_sizes[0] / (NB * 3);
    const int M = in_sizes[1] / (NB * 3);
    const int total = NB * (N + M);

    prep_kernel<<<256, 256>>>(in1, in2, N, M);

    int sBlocks = (total * 4 + 255) / 256;  // 1024 for the 8192/8192 shape
    if (sBlocks > 1024) sBlocks = 1024;     // g_part capacity (grid-stride not needed here)
    search_kernel<<<sBlocks, 256>>>(N, M, 1.f / (float)(NB * M), 1.f / (float)(NB * N));
    final_kernel<<<1, 256>>>((float*)d_out, sBlocks);
}

// round 11
// speedup vs baseline: 1.7254x; 1.7254x over previous
#include <cuda_runtime.h>
#include <math.h>
#include <float.h>

#define G 20
#define GC (G * G * G)   // 8000
#define NB 4             // batches
#define NCB 8            // cloud*NB + b
#define NPC 8192         // max points per (cloud,batch)
#define GMIN (-5.0f)
#define GH 0.5f
#define GINV 2.0f

// Static scratch (no cudaMalloc). Zero-initialized at module load; scatter_kernel
// re-zeroes g_cnt at the end of every execution so graph replays see zeros.
__device__ int g_cnt[NCB][GC];
__device__ int g_start[NCB][GC + 1];
__device__ int g_cid[NCB][NPC];
__device__ int g_rnk[NCB][NPC];
__device__ float4 g_pts[NCB][NPC];  // cell-sorted (x, y, z, |p|^2/2)
__device__ float g_part[256];

__device__ __forceinline__ int cellof(float x) {
    int c = (int)((x - GMIN) * GINV);
    return min(G - 1, max(0, c));
}

// ---------- count: cell id + rank per point (both clouds) ----------
__global__ __launch_bounds__(256) void count_kernel(const float* __restrict__ in1,
                                                    const float* __restrict__ in2,
                                                    int N, int M) {
    const int i = blockIdx.x * 256 + threadIdx.x;
    const int tot1 = NB * N;
    if (i >= tot1 + NB * M) return;
    const float* p;
    int cb, slot;
    if (i < tot1) { cb = i / N; slot = i - cb * N; p = in1 + (size_t)i * 3; }
    else {
        int j = i - tot1;
        cb = NB + j / M;
        slot = j - (cb - NB) * M;
        p = in2 + (size_t)j * 3;
    }
    const int cid = (cellof(p[2]) * G + cellof(p[1])) * G + cellof(p[0]);
    g_cid[cb][slot] = cid;
    g_rnk[cb][slot] = atomicAdd(&g_cnt[cb][cid], 1);
}

// ---------- scan: one block per (cloud,batch); 256 threads x 32 cells >= GC ----------
__global__ __launch_bounds__(256) void scan_kernel(int N, int M) {
    const int cb = blockIdx.x;
    const int tid = threadIdx.x;
    const int base = tid * 32;
    int loc = 0;
#pragma unroll 4
    for (int i = 0; i < 32; i++) {
        int c = base + i;
        if (c < GC) loc += g_cnt[cb][c];
    }
    __shared__ int sh[256];
    sh[tid] = loc;
    __syncthreads();
    for (int off = 1; off < 256; off <<= 1) {
        int v = (tid >= off) ? sh[tid - off] : 0;
        __syncthreads();
        sh[tid] += v;
        __syncthreads();
    }
    int excl = sh[tid] - loc;
#pragma unroll 4
    for (int i = 0; i < 32; i++) {
        int c = base + i;
        if (c < GC) {
            int v = g_cnt[cb][c];
            g_start[cb][c] = excl;
            excl += v;
        }
    }
    if (tid == 255) g_start[cb][GC] = sh[255];
}

// ---------- scatter into cell-sorted order (+ re-zero counters for next replay) ----------
__global__ __launch_bounds__(256) void scatter_kernel(const float* __restrict__ in1,
                                                      const float* __restrict__ in2,
                                                      int N, int M) {
    const int i = blockIdx.x * 256 + threadIdx.x;
    const int gsz = gridDim.x * 256;
    const int tot1 = NB * N;
    if (i < tot1 + NB * M) {
        const float* p;
        int cb, slot;
        if (i < tot1) { cb = i / N; slot = i - cb * N; p = in1 + (size_t)i * 3; }
        else {
            int j = i - tot1;
            cb = NB + j / M;
            slot = j - (cb - NB) * M;
            p = in2 + (size_t)j * 3;
        }
        const float x = p[0], y = p[1], z = p[2];
        const int pos = g_start[cb][g_cid[cb][slot]] + g_rnk[cb][slot];
        g_pts[cb][pos] = make_float4(x, y, z, 0.5f * (x * x + y * y + z * z));
    }
    // g_cnt is dead after scan; zero it here so the next graph replay starts clean.
    for (int j = i; j < NCB * GC; j += gsz) ((int*)g_cnt)[j] = 0;
}

// ---------- thread-per-query exact NN search + per-block deterministic sum ----------
// Box rows (z,y) are CONTIGUOUS ranges: [cs[rowb+x0], cs[rowb+x1+1]).
// t = h_p - q.p; d^2 = 2*(tmin + g_q). Unscanned cells are Chebyshev >= R+1
// away -> separation >= R*GH (boundary-clamp safe: no cells beyond the faces).
__global__ __launch_bounds__(256) void search_kernel(int N, int M,
                                                     float inv0, float inv1) {
    const int i = blockIdx.x * 256 + threadIdx.x;
    const int tot1 = NB * N;
    const int total = tot1 + NB * M;

    float contrib = 0.f;
    if (i < total) {
        int qcb, rcb;
        float wgt;
        if (i < tot1) { qcb = i / N; rcb = NB + qcb; wgt = inv1; }
        else { int j = i - tot1; qcb = NB + j / M; rcb = qcb - NB; wgt = inv0; }
        const int slot = (i < tot1) ? (i % N) : ((i - tot1) % M);

        const float4 q = g_pts[qcb][slot];  // sorted order -> warp-coherent cells
        const float nqx = -q.x, nqy = -q.y, nqz = -q.z, gq = q.w;
        const int cx = cellof(q.x), cy = cellof(q.y), cz = cellof(q.z);

        const float4* __restrict__ pts = g_pts[rcb];
        const int* __restrict__ cs = g_start[rcb];

        float tmin = FLT_MAX;
        float best;
        int R = 1;
        for (;; R++) {
            const int z0 = max(cz - R, 0), z1 = min(cz + R, G - 1);
            const int y0 = max(cy - R, 0), y1 = min(cy + R, G - 1);
            const int x0 = max(cx - R, 0), x1 = min(cx + R, G - 1);
            for (int z = z0; z <= z1; z++) {
                for (int y = y0; y <= y1; y++) {
                    const int rowb = (z * G + y) * G;
                    const int s = cs[rowb + x0];
                    const int e = cs[rowb + x1 + 1];
                    for (int k = s; k < e; k++) {
                        float4 p = pts[k];
                        float t = fmaf(p.x, nqx, fmaf(p.y, nqy, fmaf(p.z, nqz, p.w)));
                        tmin = fminf(tmin, t);
                    }
                }
            }
            best = fmaxf(0.f, 2.f * (tmin + gq));
            const float bd = (float)R * GH;
            if (best <= bd * bd || R >= G) break;
        }
        contrib = sqrtf(best) * wgt;
    }

    // Deterministic per-block reduction (fixed thread->query mapping).
    float acc = contrib;
#pragma unroll
    for (int off = 16; off > 0; off >>= 1)
        acc += __shfl_down_sync(0xFFFFFFFFu, acc, off);
    __shared__ float shf[8];
    if ((threadIdx.x & 31) == 0) shf[threadIdx.x >> 5] = acc;
    __syncthreads();
    if (threadIdx.x < 8) {
        float v = shf[threadIdx.x];
#pragma unroll
        for (int off = 4; off > 0; off >>= 1)
            v += __shfl_down_sync(0xFFu, v, off);
        if (threadIdx.x == 0) g_part[blockIdx.x] = v;
    }
}

// ---------- final: fixed-order sum of block partials ----------
__global__ void final_kernel(float* __restrict__ out, int nPart) {
    float a = 0.f;
    for (int k = threadIdx.x; k < nPart; k += 256) a += g_part[k];
#pragma unroll
    for (int off = 16; off > 0; off >>= 1)
        a += __shfl_down_sync(0xFFFFFFFFu, a, off);
    __shared__ float s[8];
    if ((threadIdx.x & 31) == 0) s[threadIdx.x >> 5] = a;
    __syncthreads();
    if (threadIdx.x < 8) {
        float v = s[threadIdx.x];
#pragma unroll
        for (int off = 4; off > 0; off >>= 1)
            v += __shfl_down_sync(0xFFu, v, off);
        if (threadIdx.x == 0) out[0] = v;
    }
}

extern "C" void kernel_launch(void* const* d_in, const int* in_sizes, int n_in,
                              void* d_out, int out_size) {
    const float* in1 = (const float*)d_in[0];  // [B, N, 3] cloud1
    const float* in2 = (const float*)d_in[1];  // [B, M, 3] cloud2
    const int N = in_sizes[0] / (NB * 3);
    const int M = in_sizes[1] / (NB * 3);
    const int total = NB * (N + M);
    const int nBlocks = (total + 255) / 256;  // 256 for the 8192/8192 shape

    count_kernel<<<nBlocks, 256>>>(in1, in2, N, M);
    scan_kernel<<<NCB, 256>>>(N, M);
    scatter_kernel<<<nBlocks, 256>>>(in1, in2, N, M);
    search_kernel<<<nBlocks, 256>>>(N, M, 1.f / (float)(NB * M), 1.f / (float)(NB * N));
    final_kernel<<<1, 256>>>((float*)d_out, nBlocks);
}